// round 3
// baseline (speedup 1.0000x reference)
#include <cuda_runtime.h>
#include <cuda_bf16.h>

// ZBL screened nuclear repulsion:
//   expv = Dij/d * (Zi^p + Zj^p)
//   vij  = sum_k c[k] * exp(-a[k]*expv)
//   out  = segment_sum(vij, idx_i)   (idx_i sorted)
//
// Inputs (metadata order):
//   0: Z     int32  [500000]
//   1: Dij   f32    [16000000]
//   2: idx_i int32  [16000000]   (sorted)
//   3: idx_j int32  [16000000]
//   4: p     f32    [1]
//   5: d     f32    [1]
//   6: c     f32    [4]
//   7: a     f32    [4]
// Output: f32 [500000]

#define MAX_Z   94
#define EPT     4      // edges per thread
#define TPB     256

__device__ float g_zp[MAX_Z];      // z^p lookup
__device__ float g_params[12];     // [0]=1/d, [1..4]=c, [5..8]=b_k=-a_k*log2(e)

// ---------------------------------------------------------------------------
// Init kernel: zero the (poisoned) output, build z^p table + derived params.
// ---------------------------------------------------------------------------
__global__ void zbl_init_kernel(const float* __restrict__ p_ptr,
                                const float* __restrict__ d_ptr,
                                const float* __restrict__ c_ptr,
                                const float* __restrict__ a_ptr,
                                float* __restrict__ out, int n_out)
{
    int t = blockIdx.x * blockDim.x + threadIdx.x;
    if (t < n_out) out[t] = 0.0f;

    if (blockIdx.x == 0) {
        if (threadIdx.x < MAX_Z) {
            float p = *p_ptr;
            g_zp[threadIdx.x] = powf((float)threadIdx.x, p);
        }
        if (threadIdx.x == 0) {
            const float L2E = 1.4426950408889634f;
            g_params[0] = 1.0f / (*d_ptr);
            #pragma unroll
            for (int k = 0; k < 4; k++) {
                g_params[1 + k] = c_ptr[k];
                g_params[5 + k] = -a_ptr[k] * L2E;
            }
        }
    }
}

__device__ __forceinline__ float ex2(float x) {
    float y;
    asm("ex2.approx.f32 %0, %1;" : "=f"(y) : "f"(x));
    return y;
}

// ---------------------------------------------------------------------------
// Main kernel: 4 edges/thread, vectorized loads, shared zp table,
// per-thread run merge + warp-segmented shuffle scan, boundary atomics only.
// ---------------------------------------------------------------------------
__global__ __launch_bounds__(TPB)
void zbl_main_kernel(const float* __restrict__ Dij,
                     const int*   __restrict__ idx_i,
                     const int*   __restrict__ idx_j,
                     const int*   __restrict__ Z,
                     float*       __restrict__ out,
                     int E)
{
    __shared__ float s_zp[MAX_Z + 2];
    __shared__ float s_par[12];
    if (threadIdx.x < MAX_Z) s_zp[threadIdx.x] = g_zp[threadIdx.x];
    if (threadIdx.x < 12)    s_par[threadIdx.x] = g_params[threadIdx.x];
    __syncthreads();

    const float invd = s_par[0];
    const float c0 = s_par[1], c1 = s_par[2], c2 = s_par[3], c3 = s_par[4];
    const float b0 = s_par[5], b1 = s_par[6], b2 = s_par[7], b3 = s_par[8];

    const int tid  = blockIdx.x * blockDim.x + threadIdx.x;
    const int base = tid * EPT;

    int   cur = -1;     // pending segment id (tail)
    float acc = 0.0f;   // pending segment sum

    if (base + EPT <= E) {
        // ---- fast vector path: all front-batched loads for MLP ----
        const float4 dd = __ldg(reinterpret_cast<const float4*>(Dij)   + tid);
        const int4   ii = __ldg(reinterpret_cast<const int4*>(idx_i)   + tid);
        const int4   jj = __ldg(reinterpret_cast<const int4*>(idx_j)   + tid);

        const int zi0 = __ldg(Z + ii.x), zi1 = __ldg(Z + ii.y);
        const int zi2 = __ldg(Z + ii.z), zi3 = __ldg(Z + ii.w);
        const int zj0 = __ldg(Z + jj.x), zj1 = __ldg(Z + jj.y);
        const int zj2 = __ldg(Z + jj.z), zj3 = __ldg(Z + jj.w);

        const float e0 = dd.x * invd * (s_zp[zi0] + s_zp[zj0]);
        const float e1 = dd.y * invd * (s_zp[zi1] + s_zp[zj1]);
        const float e2 = dd.z * invd * (s_zp[zi2] + s_zp[zj2]);
        const float e3 = dd.w * invd * (s_zp[zi3] + s_zp[zj3]);

        const float v0 = c0*ex2(b0*e0) + c1*ex2(b1*e0) + c2*ex2(b2*e0) + c3*ex2(b3*e0);
        const float v1 = c0*ex2(b0*e1) + c1*ex2(b1*e1) + c2*ex2(b2*e1) + c3*ex2(b3*e1);
        const float v2 = c0*ex2(b0*e2) + c1*ex2(b1*e2) + c2*ex2(b2*e2) + c3*ex2(b3*e2);
        const float v3 = c0*ex2(b0*e3) + c1*ex2(b1*e3) + c2*ex2(b2*e3) + c3*ex2(b3*e3);

        // sequential merge of the 4 sorted edges (flush interior runs directly)
        cur = ii.x; acc = v0;
        if (ii.y == cur) acc += v1; else { atomicAdd(out + cur, acc); cur = ii.y; acc = v1; }
        if (ii.z == cur) acc += v2; else { atomicAdd(out + cur, acc); cur = ii.z; acc = v2; }
        if (ii.w == cur) acc += v3; else { atomicAdd(out + cur, acc); cur = ii.w; acc = v3; }
    } else if (base < E) {
        // ---- remainder path (E not multiple of EPT): scalar, direct atomics ----
        for (int e = base; e < E; e++) {
            const int   si = __ldg(idx_i + e);
            const int   sj = __ldg(idx_j + e);
            const float ev = __ldg(Dij + e) * invd * (s_zp[__ldg(Z + si)] + s_zp[__ldg(Z + sj)]);
            const float v  = c0*ex2(b0*ev) + c1*ex2(b1*ev) + c2*ex2(b2*ev) + c3*ex2(b3*ev);
            atomicAdd(out + si, v);
        }
        cur = -1; acc = 0.0f;  // nothing pending for the warp scan
    }

    // ---- warp-level segmented inclusive scan over the pending tails ----
    // idx_i is sorted, so tail ids are non-decreasing across lanes; equal-id
    // runs are contiguous. The last lane of each run issues one atomicAdd.
    const unsigned m = 0xFFFFFFFFu;
    const int lane = threadIdx.x & 31;
    #pragma unroll
    for (int o = 1; o < 32; o <<= 1) {
        const float vv = __shfl_up_sync(m, acc, o);
        const int   ss = __shfl_up_sync(m, cur, o);
        if (lane >= o && ss == cur) acc += vv;
    }
    const int nxt = __shfl_down_sync(m, cur, 1);
    if (cur >= 0 && (lane == 31 || nxt != cur)) {
        atomicAdd(out + cur, acc);
    }
}

// ---------------------------------------------------------------------------
extern "C" void kernel_launch(void* const* d_in, const int* in_sizes, int n_in,
                              void* d_out, int out_size)
{
    const int*   Z     = (const int*)  d_in[0];
    const float* Dij   = (const float*)d_in[1];
    const int*   idx_i = (const int*)  d_in[2];
    const int*   idx_j = (const int*)  d_in[3];
    const float* p_ptr = (const float*)d_in[4];
    const float* d_ptr = (const float*)d_in[5];
    const float* c_ptr = (const float*)d_in[6];
    const float* a_ptr = (const float*)d_in[7];
    float* out = (float*)d_out;

    const int E = in_sizes[1];
    const int N = out_size;

    // 1) zero output (poisoned by harness) + build z^p table / params
    {
        const int blocks = (N + TPB - 1) / TPB;
        zbl_init_kernel<<<blocks, TPB>>>(p_ptr, d_ptr, c_ptr, a_ptr, out, N);
    }

    // 2) fused edge compute + sorted segment reduction
    {
        const int threads = (E + EPT - 1) / EPT;
        const int blocks  = (threads + TPB - 1) / TPB;
        zbl_main_kernel<<<blocks, TPB>>>(Dij, idx_i, idx_j, Z, out, E);
    }
}